// round 4
// baseline (speedup 1.0000x reference)
#include <cuda_runtime.h>
#include <cuda_bf16.h>
#include <math_constants.h>
#include <cstdint>

// Problem dims (fixed by dataset)
#define SS  128
#define HH  8
#define QL  256
#define DHD 32
#define CC  256
#define M_TOT (SS * QL)
#define KH  (CC / 2)      // uint2 (hi-pair, lo-pair) elements per row = 128

// ---------------- scratch (device globals; no allocation allowed) ----------
__device__ float g_q[SS * HH * QL * DHD];     // [s,h,q,dh] fp32
__device__ float g_k[SS * HH * QL * DHD];
__device__ float g_v[SS * HH * QL * DHD];
__device__ float g_g[M_TOT * CC];             // gate fp32
__device__ uint2 g_qxP[M_TOT * KH];           // packed hi/lo bf16 of q_x
__device__ uint2 g_kvxP[M_TOT * KH];          // packed kv_x
__device__ uint2 g_oP[M_TOT * KH];            // packed gated attention out
__device__ uint2 g_WqP[CC * KH];
__device__ uint2 g_WkP[CC * KH];
__device__ uint2 g_WvP[CC * KH];
__device__ uint2 g_WgP[CC * KH];
__device__ uint2 g_WoP[CC * KH];

// ---------------- packing: fp32 pair -> {bf16 hi pair, bf16 lo pair} -------
__device__ __forceinline__ uint2 pack_hilo(float x, float y) {
    __nv_bfloat162 h = __floats2bfloat162_rn(x, y);
    float hx = __bfloat162float(h.x);
    float hy = __bfloat162float(h.y);
    __nv_bfloat162 l = __floats2bfloat162_rn(x - hx, y - hy);
    uint2 r;
    r.x = *reinterpret_cast<uint32_t*>(&h);
    r.y = *reinterpret_cast<uint32_t*>(&l);
    return r;
}

__global__ __launch_bounds__(256) void pack_k(const float* __restrict__ in,
                                              uint2* __restrict__ out, int n2) {
    for (int i = blockIdx.x * blockDim.x + threadIdx.x; i < n2;
         i += gridDim.x * blockDim.x) {
        float2 v = ((const float2*)in)[i];
        out[i] = pack_hilo(v.x, v.y);
    }
}

// ---------------- warp-level bf16 MMA (base ISA, compiles on compute_103) --
__device__ __forceinline__ void mma16816(float* d, uint32_t a0, uint32_t a1,
                                         uint32_t a2, uint32_t a3,
                                         uint32_t b0, uint32_t b1) {
    asm volatile(
        "mma.sync.aligned.m16n8k16.row.col.f32.bf16.bf16.f32 "
        "{%0,%1,%2,%3}, {%4,%5,%6,%7}, {%8,%9}, {%0,%1,%2,%3};\n"
        : "+f"(d[0]), "+f"(d[1]), "+f"(d[2]), "+f"(d[3])
        : "r"(a0), "r"(a1), "r"(a2), "r"(a3), "r"(b0), "r"(b1));
}

// =================== GEMM: C[m,n] = sum_k X[m,k]*W[n,k] ====================
// X packed [M, KH] uint2, W packed [CC, KH] uint2.
// 3-term split: hi*hi + hi*lo + lo*hi, fp32 accumulate.
// CTA: 128 threads (4 warps), tile 64(M) x 128(N); warp tile 64 x 32.
// MODE 0: head-interleaved scatter  MODE 1: sigmoid(c+bias)  MODE 2: c+bias
template <int MODE>
__global__ __launch_bounds__(128)
void gemm_mma(const uint2* __restrict__ Xp, const uint2* __restrict__ Wp,
              const float* __restrict__ bias, float* __restrict__ out) {
    const int bm = blockIdx.y * 64;
    const int bn = blockIdx.x * 128;
    const int warp = threadIdx.x >> 5;
    const int lane = threadIdx.x & 31;
    const int grp = lane >> 2;          // 0..7
    const int tig = lane & 3;           // 0..3
    const int wn = bn + warp * 32;

    const uint2* Ab = Xp + (bm + grp) * KH + tig;
    const uint2* Bb = Wp + (wn + grp) * KH + tig;

    float d[4][4][4];
#pragma unroll
    for (int i = 0; i < 4; i++)
#pragma unroll
        for (int j = 0; j < 4; j++)
#pragma unroll
            for (int e = 0; e < 4; e++) d[i][j][e] = 0.0f;

#pragma unroll 4
    for (int ks = 0; ks < 16; ks++) {
        const int kp = ks * 8;
        uint2 a[4][4];
#pragma unroll
        for (int i = 0; i < 4; i++) {
            const uint2* p = Ab + (16 * i) * KH + kp;
            a[i][0] = p[0];
            a[i][1] = p[8 * KH];
            a[i][2] = p[4];
            a[i][3] = p[8 * KH + 4];
        }
        uint2 b[4][2];
#pragma unroll
        for (int j = 0; j < 4; j++) {
            const uint2* p = Bb + (8 * j) * KH + kp;
            b[j][0] = p[0];
            b[j][1] = p[4];
        }
#pragma unroll
        for (int i = 0; i < 4; i++)
#pragma unroll
            for (int j = 0; j < 4; j++) {
                mma16816(d[i][j], a[i][0].x, a[i][1].x, a[i][2].x, a[i][3].x,
                         b[j][0].x, b[j][1].x);                       // hi*hi
                mma16816(d[i][j], a[i][0].x, a[i][1].x, a[i][2].x, a[i][3].x,
                         b[j][0].y, b[j][1].y);                       // hi*lo
                mma16816(d[i][j], a[i][0].y, a[i][1].y, a[i][2].y, a[i][3].y,
                         b[j][0].x, b[j][1].x);                       // lo*hi
            }
    }

    // epilogue
#pragma unroll
    for (int i = 0; i < 4; i++) {
        const int r0 = bm + 16 * i + grp;
#pragma unroll
        for (int j = 0; j < 4; j++) {
            const int n = wn + 8 * j + 2 * tig;
#pragma unroll
            for (int half = 0; half < 2; half++) {
                const int row = r0 + half * 8;
                float v0 = d[i][j][2 * half];
                float v1 = d[i][j][2 * half + 1];
                if (MODE == 0) {
                    const int h = n >> 5, dh = n & 31;
                    const int s = row >> 8, q = row & 255;
                    float* op = out + (((s * HH + h) * QL) + q) * DHD + dh;
                    *(float2*)op = make_float2(v0, v1);
                } else {
                    v0 += bias[n];
                    v1 += bias[n + 1];
                    if (MODE == 1) {
                        v0 = 1.0f / (1.0f + __expf(-v0));
                        v1 = 1.0f / (1.0f + __expf(-v1));
                    }
                    *(float2*)(out + row * CC + n) = make_float2(v0, v1);
                }
            }
        }
    }
}

// =================== attention (SIMT flash, packed output) =================
__global__ __launch_bounds__(256) void attn_k(const float* __restrict__ qb,
                                              const float* __restrict__ kb,
                                              const float* __restrict__ vb,
                                              const float* __restrict__ bias_mask,
                                              const float* __restrict__ bias_pair,
                                              const float* __restrict__ gbuf,
                                              uint2* __restrict__ obufP) {
    extern __shared__ float sm[];
    float* Ks = sm;
    float* Vs = sm + QL * DHD;
    float* bms = sm + 2 * QL * DHD;

    const int sh = blockIdx.x;
    const int s = sh >> 3, h = sh & 7;
    const int tid = threadIdx.x;

    const float* kp = kb + sh * (QL * DHD);
    const float* vp = vb + sh * (QL * DHD);
    for (int i = tid * 4; i < QL * DHD; i += 1024) {
        *(float4*)(Ks + i) = *(const float4*)(kp + i);
        *(float4*)(Vs + i) = *(const float4*)(vp + i);
    }
    bms[tid] = bias_mask[s * QL + tid];
    __syncthreads();

    float qr[DHD];
    const float* qp = qb + (sh * QL + tid) * DHD;
#pragma unroll
    for (int d = 0; d < DHD; d += 4) {
        float4 t = *(const float4*)(qp + d);
        qr[d] = t.x; qr[d + 1] = t.y; qr[d + 2] = t.z; qr[d + 3] = t.w;
    }
    const float* bp = bias_pair + (h * QL + tid) * QL;

    float mrun = -CUDART_INF_F, lrun = 0.0f;
    float acc[DHD];
#pragma unroll
    for (int d = 0; d < DHD; d++) acc[d] = 0.0f;

    for (int kt = 0; kt < QL; kt += 32) {
        float sc[32];
#pragma unroll
        for (int kk = 0; kk < 32; kk++) {
            float sum = bms[kt + kk] + bp[kt + kk];
            const float* kr = Ks + (kt + kk) * DHD;
#pragma unroll
            for (int d = 0; d < DHD; d += 4) {
                float4 kv = *(const float4*)(kr + d);
                sum = fmaf(qr[d],     kv.x, sum);
                sum = fmaf(qr[d + 1], kv.y, sum);
                sum = fmaf(qr[d + 2], kv.z, sum);
                sum = fmaf(qr[d + 3], kv.w, sum);
            }
            sc[kk] = sum;
        }
        float tmax = mrun;
#pragma unroll
        for (int kk = 0; kk < 32; kk++) tmax = fmaxf(tmax, sc[kk]);
        const float rescale = __expf(mrun - tmax);
        lrun *= rescale;
#pragma unroll
        for (int d = 0; d < DHD; d++) acc[d] *= rescale;
#pragma unroll
        for (int kk = 0; kk < 32; kk++) {
            const float w = __expf(sc[kk] - tmax);
            lrun += w;
            const float* vr = Vs + (kt + kk) * DHD;
#pragma unroll
            for (int d = 0; d < DHD; d += 4) {
                float4 vv = *(const float4*)(vr + d);
                acc[d]     = fmaf(w, vv.x, acc[d]);
                acc[d + 1] = fmaf(w, vv.y, acc[d + 1]);
                acc[d + 2] = fmaf(w, vv.z, acc[d + 2]);
                acc[d + 3] = fmaf(w, vv.w, acc[d + 3]);
            }
        }
        mrun = tmax;
    }

    const float inv = 1.0f / lrun;
    const int mrow = s * QL + tid;
    const float* gp = gbuf + mrow * CC + h * DHD;
    uint2* op = obufP + mrow * KH + h * (DHD / 2);
#pragma unroll
    for (int d = 0; d < DHD; d += 2) {
        float2 gg = *(const float2*)(gp + d);
        float v0 = acc[d] * inv * gg.x;
        float v1 = acc[d + 1] * inv * gg.y;
        op[d / 2] = pack_hilo(v0, v1);
    }
}

// =================== launch ================================================
extern "C" void kernel_launch(void* const* d_in, const int* in_sizes, int n_in,
                              void* d_out, int out_size) {
    const float* q_x       = (const float*)d_in[0];
    const float* kv_x      = (const float*)d_in[1];
    const float* bias_mask = (const float*)d_in[2];
    const float* bias_pair = (const float*)d_in[3];
    const float* Wq        = (const float*)d_in[4];
    const float* Wk        = (const float*)d_in[5];
    const float* Wv        = (const float*)d_in[6];
    const float* Wg        = (const float*)d_in[7];
    const float* bg        = (const float*)d_in[8];
    const float* Wo        = (const float*)d_in[9];
    const float* bo        = (const float*)d_in[10];
    float* out = (float*)d_out;

    float *qb, *kb, *vb, *gb;
    uint2 *qxP, *kvxP, *oP, *WqP, *WkP, *WvP, *WgP, *WoP;
    cudaGetSymbolAddress((void**)&qb,   g_q);
    cudaGetSymbolAddress((void**)&kb,   g_k);
    cudaGetSymbolAddress((void**)&vb,   g_v);
    cudaGetSymbolAddress((void**)&gb,   g_g);
    cudaGetSymbolAddress((void**)&qxP,  g_qxP);
    cudaGetSymbolAddress((void**)&kvxP, g_kvxP);
    cudaGetSymbolAddress((void**)&oP,   g_oP);
    cudaGetSymbolAddress((void**)&WqP,  g_WqP);
    cudaGetSymbolAddress((void**)&WkP,  g_WkP);
    cudaGetSymbolAddress((void**)&WvP,  g_WvP);
    cudaGetSymbolAddress((void**)&WgP,  g_WgP);
    cudaGetSymbolAddress((void**)&WoP,  g_WoP);

    const int nx2 = M_TOT * KH;   // 4194304 pairs
    const int nw2 = CC * KH;      // 32768 pairs

    pack_k<<<512, 256>>>(q_x,  qxP,  nx2);
    pack_k<<<512, 256>>>(kv_x, kvxP, nx2);
    pack_k<<<32, 256>>>(Wq, WqP, nw2);
    pack_k<<<32, 256>>>(Wk, WkP, nw2);
    pack_k<<<32, 256>>>(Wv, WvP, nw2);
    pack_k<<<32, 256>>>(Wg, WgP, nw2);
    pack_k<<<32, 256>>>(Wo, WoP, nw2);

    const dim3 grid(CC / 128, M_TOT / 64);   // (2, 512)

    gemm_mma<0><<<grid, 128>>>(qxP,  WqP, nullptr, qb);
    gemm_mma<0><<<grid, 128>>>(kvxP, WkP, nullptr, kb);
    gemm_mma<0><<<grid, 128>>>(kvxP, WvP, nullptr, vb);
    gemm_mma<1><<<grid, 128>>>(qxP,  WgP, bg,      gb);

    const int smem_attn = (2 * QL * DHD + QL) * (int)sizeof(float);  // 66.5 KB
    cudaFuncSetAttribute(attn_k, cudaFuncAttributeMaxDynamicSharedMemorySize, smem_attn);
    attn_k<<<SS * HH, 256, smem_attn>>>(qb, kb, vb, bias_mask, bias_pair, gb, oP);

    gemm_mma<2><<<grid, 128>>>(oP, WoP, bo, out);
}

// round 9
// speedup vs baseline: 1.9826x; 1.9826x over previous
#include <cuda_runtime.h>
#include <cuda_bf16.h>
#include <math_constants.h>
#include <cstdint>

// Problem dims (fixed by dataset)
#define SS  128
#define HH  8
#define QL  256
#define DHD 32
#define CC  256
#define M_TOT (SS * QL)
#define KU2 (CC / 2)          // uint2 (2 k-elems) per row = 128

// ---------------- scratch (device globals; no allocation allowed) ----------
__device__ float g_q[SS * HH * QL * DHD];     // [s,h,q,dh] fp32
__device__ float g_k[SS * HH * QL * DHD];
__device__ float g_v[SS * HH * QL * DHD];
__device__ float g_g[M_TOT * CC];             // gate fp32
__device__ float g_o[M_TOT * CC];             // gated attention out fp32
__device__ float g_bpT[HH * QL * QL];         // bias_pair transposed [h,k,q]

// Fragment-major packed buffers.
// A-frag: per (mb = m/16, kb = k16 block 0..15): 32 lanes x 4 uint2 (lane-major)
__device__ uint4 g_qxA[M_TOT / 16 * 16 * 32 * 2];
__device__ uint4 g_kvxA[M_TOT / 16 * 16 * 32 * 2];
__device__ uint4 g_oA[M_TOT / 16 * 16 * 32 * 2];
// B-frag: per (jb = n/8 0..31, kb 0..15): 32 lanes x 1 uint4
__device__ uint4 g_WqB[32 * 16 * 32];
__device__ uint4 g_WkB[32 * 16 * 32];
__device__ uint4 g_WvB[32 * 16 * 32];
__device__ uint4 g_WgB[32 * 16 * 32];
__device__ uint4 g_WoB[32 * 16 * 32];

// ---------------- fast math (FMA-pipe exp / rcp; avoid MUFU) ---------------
__device__ __forceinline__ float fexp(float x) {
    x = fmaxf(x, -87.0f);                      // exp(-87) ~ 1.6e-38; -inf safe
    const float t = x * 1.4426950408889634f;
    const float r = t + 12582912.0f;           // round-to-nearest in low bits
    const int   i = __float_as_int(r);
    const float f = t - (r - 12582912.0f);     // f in [-0.5, 0.5]
    float p = 1.3333558146e-3f;
    p = fmaf(f, p, 9.6181291076e-3f);
    p = fmaf(f, p, 5.5504108664e-2f);
    p = fmaf(f, p, 2.4022650696e-1f);
    p = fmaf(f, p, 6.9314718056e-1f);
    p = fmaf(f, p, 1.0f);                      // p = 2^f
    return __int_as_float(__float_as_int(p) + (i << 23));   // * 2^round(t)
}
__device__ __forceinline__ float frcp_fast(float a) {   // a in (1, 2]
    float y = __int_as_float(0x7EF311C7 - __float_as_int(a));
    y = y * fmaf(-a, y, 2.0f);
    y = y * fmaf(-a, y, 2.0f);
    y = y * fmaf(-a, y, 2.0f);
    return y;
}
__device__ __forceinline__ float fsigmoid(float v) {
    const float e = fexp(-fabsf(v));
    const float r = frcp_fast(1.0f + e);
    return v >= 0.0f ? r : e * r;
}

// ---------------- packing: fp32 pair -> {bf16 hi pair, bf16 lo pair} -------
__device__ __forceinline__ uint2 pack_hilo(float x, float y) {
    __nv_bfloat162 h = __floats2bfloat162_rn(x, y);
    float hx = __bfloat162float(h.x);
    float hy = __bfloat162float(h.y);
    __nv_bfloat162 l = __floats2bfloat162_rn(x - hx, y - hy);
    uint2 r;
    r.x = *reinterpret_cast<uint32_t*>(&h);
    r.y = *reinterpret_cast<uint32_t*>(&l);
    return r;
}

// A-frag pack: in fp32 [M,256] row-major -> g_*A layout. One thread = 1 uint2.
__global__ __launch_bounds__(256) void packA_k(const float* __restrict__ in,
                                               uint2* __restrict__ out) {
    const int t = blockIdx.x * blockDim.x + threadIdx.x;   // 0 .. M*128-1
    const int r    = t & 3;
    const int lane = (t >> 2) & 31;
    const int kb   = (t >> 7) & 15;
    const int mb   = t >> 11;
    const int grp = lane >> 2, tig = lane & 3;
    const int row = mb * 16 + grp + (r & 1) * 8;
    const int ku2 = kb * 8 + (r >> 1) * 4 + tig;
    const float2 v = ((const float2*)in)[row * KU2 + ku2];
    out[t] = pack_hilo(v.x, v.y);
}

// B-frag pack for all 5 weight matrices in one launch (blockIdx.y selects).
__global__ __launch_bounds__(256) void packB5_k(const float* __restrict__ W0,
                                                const float* __restrict__ W1,
                                                const float* __restrict__ W2,
                                                const float* __restrict__ W3,
                                                const float* __restrict__ W4) {
    const float* src;
    uint4* dst;
    switch (blockIdx.y) {
        case 0: src = W0; dst = g_WqB; break;
        case 1: src = W1; dst = g_WkB; break;
        case 2: src = W2; dst = g_WvB; break;
        case 3: src = W3; dst = g_WgB; break;
        default: src = W4; dst = g_WoB; break;
    }
    const int t = blockIdx.x * blockDim.x + threadIdx.x;   // 0..16383
    const int lane = t & 31;
    const int kb   = (t >> 5) & 15;
    const int jb   = t >> 9;
    const int grp = lane >> 2, tig = lane & 3;
    const int n = jb * 8 + grp;
    const float2 v0 = ((const float2*)src)[n * KU2 + kb * 8 + tig];
    const float2 v1 = ((const float2*)src)[n * KU2 + kb * 8 + 4 + tig];
    const uint2 p0 = pack_hilo(v0.x, v0.y);
    const uint2 p1 = pack_hilo(v1.x, v1.y);
    dst[t] = make_uint4(p0.x, p0.y, p1.x, p1.y);
}

// bias_pair [h,q,k] -> [h,k,q] tiled transpose (32x32 tiles, 32x8 threads)
__global__ __launch_bounds__(256) void transBP_k(const float* __restrict__ bp,
                                                 float* __restrict__ bpT) {
    __shared__ float tile[32][33];
    const int h = blockIdx.z;
    const int q0 = blockIdx.y * 32;
    const int k0 = blockIdx.x * 32;
    const int tx = threadIdx.x & 31, ty = threadIdx.x >> 5;
#pragma unroll
    for (int i = 0; i < 4; i++)
        tile[ty + i * 8][tx] = bp[(h * QL + q0 + ty + i * 8) * QL + k0 + tx];
    __syncthreads();
#pragma unroll
    for (int i = 0; i < 4; i++)
        bpT[(h * QL + k0 + ty + i * 8) * QL + q0 + tx] = tile[tx][ty + i * 8];
}

// ---------------- warp-level bf16 MMA (base ISA) ---------------------------
__device__ __forceinline__ void mma16816(float* d, uint32_t a0, uint32_t a1,
                                         uint32_t a2, uint32_t a3,
                                         uint32_t b0, uint32_t b1) {
    asm volatile(
        "mma.sync.aligned.m16n8k16.row.col.f32.bf16.bf16.f32 "
        "{%0,%1,%2,%3}, {%4,%5,%6,%7}, {%8,%9}, {%0,%1,%2,%3};\n"
        : "+f"(d[0]), "+f"(d[1]), "+f"(d[2]), "+f"(d[3])
        : "r"(a0), "r"(a1), "r"(a2), "r"(a3), "r"(b0), "r"(b1));
}

// =================== GEMM: C[m,n] = sum_k X[m,k]*W[n,k] ====================
// A-frag/B-frag inputs, 3-term split, fp32 accum.
// CTA 128 thr (4 warps): tile 64(M) x 128(N); warp tile 64 x 32.
// MODE 0: head-interleaved scatter  MODE 1: sigmoid(c+bias)  MODE 2: c+bias
template <int MODE>
__global__ __launch_bounds__(128)
void gemm_mma(const uint4* __restrict__ Af, const uint4* __restrict__ Bf,
              const float* __restrict__ bias, float* __restrict__ out) {
    const int bm = blockIdx.y * 64;
    const int bn = blockIdx.x * 128;
    const int warp = threadIdx.x >> 5;
    const int lane = threadIdx.x & 31;
    const int grp = lane >> 2;
    const int tig = lane & 3;
    const int wn = bn + warp * 32;
    const int mb0 = bm >> 4;
    const int jb0 = wn >> 3;

    float d[4][4][4];
#pragma unroll
    for (int i = 0; i < 4; i++)
#pragma unroll
        for (int j = 0; j < 4; j++)
#pragma unroll
            for (int e = 0; e < 4; e++) d[i][j][e] = 0.0f;

#pragma unroll 4
    for (int kb = 0; kb < 16; kb++) {
        uint4 aq[4][2];
#pragma unroll
        for (int i = 0; i < 4; i++) {
            const uint4* p = Af + ((mb0 + i) * 16 + kb) * 64 + lane * 2;
            aq[i][0] = p[0];
            aq[i][1] = p[1];
        }
        uint4 bq[4];
#pragma unroll
        for (int j = 0; j < 4; j++)
            bq[j] = Bf[((jb0 + j) * 16 + kb) * 32 + lane];
#pragma unroll
        for (int i = 0; i < 4; i++)
#pragma unroll
            for (int j = 0; j < 4; j++) {
                mma16816(d[i][j], aq[i][0].x, aq[i][0].z, aq[i][1].x, aq[i][1].z,
                         bq[j].x, bq[j].z);                       // hi*hi
                mma16816(d[i][j], aq[i][0].x, aq[i][0].z, aq[i][1].x, aq[i][1].z,
                         bq[j].y, bq[j].w);                       // hi*lo
                mma16816(d[i][j], aq[i][0].y, aq[i][0].w, aq[i][1].y, aq[i][1].w,
                         bq[j].x, bq[j].z);                       // lo*hi
            }
    }

    // epilogue
#pragma unroll
    for (int i = 0; i < 4; i++) {
        const int r0 = bm + 16 * i + grp;
#pragma unroll
        for (int j = 0; j < 4; j++) {
            const int n = wn + 8 * j + 2 * tig;
#pragma unroll
            for (int half = 0; half < 2; half++) {
                const int row = r0 + half * 8;
                float v0 = d[i][j][2 * half];
                float v1 = d[i][j][2 * half + 1];
                if (MODE == 0) {
                    const int h = n >> 5, dh = n & 31;
                    const int s = row >> 8, q = row & 255;
                    float* op = out + (((s * HH + h) * QL) + q) * DHD + dh;
                    *(float2*)op = make_float2(v0, v1);
                } else {
                    v0 += bias[n];
                    v1 += bias[n + 1];
                    if (MODE == 1) {
                        v0 = fsigmoid(v0);
                        v1 = fsigmoid(v1);
                    }
                    *(float2*)(out + row * CC + n) = make_float2(v0, v1);
                }
            }
        }
    }
}

// =================== attention (SIMT flash, poly-exp, coalesced bias) ======
__global__ __launch_bounds__(256) void attn_k(const float* __restrict__ qb,
                                              const float* __restrict__ kb,
                                              const float* __restrict__ vb,
                                              const float* __restrict__ bias_mask,
                                              const float* __restrict__ bpT,
                                              const float* __restrict__ gbuf,
                                              float* __restrict__ obuf) {
    extern __shared__ float sm[];
    float* Ks = sm;
    float* Vs = sm + QL * DHD;
    float* bms = sm + 2 * QL * DHD;

    const int sh = blockIdx.x;
    const int s = sh >> 3, h = sh & 7;
    const int tid = threadIdx.x;

    const float* kp = kb + sh * (QL * DHD);
    const float* vp = vb + sh * (QL * DHD);
    for (int i = tid * 4; i < QL * DHD; i += 1024) {
        *(float4*)(Ks + i) = *(const float4*)(kp + i);
        *(float4*)(Vs + i) = *(const float4*)(vp + i);
    }
    bms[tid] = bias_mask[s * QL + tid];
    __syncthreads();

    float qr[DHD];
    const float* qp = qb + (sh * QL + tid) * DHD;
#pragma unroll
    for (int d = 0; d < DHD; d += 4) {
        float4 t = *(const float4*)(qp + d);
        qr[d] = t.x; qr[d + 1] = t.y; qr[d + 2] = t.z; qr[d + 3] = t.w;
    }
    const float* bpc = bpT + (h * QL) * QL + tid;   // [k][q=tid], coalesced

    float mrun = -CUDART_INF_F, lrun = 0.0f;
    float acc[DHD];
#pragma unroll
    for (int d = 0; d < DHD; d++) acc[d] = 0.0f;

    for (int kt = 0; kt < QL; kt += 32) {
        float sc[32];
#pragma unroll
        for (int kk = 0; kk < 32; kk++) {
            float sum = bms[kt + kk] + bpc[(kt + kk) * QL];
            const float* kr = Ks + (kt + kk) * DHD;
#pragma unroll
            for (int d = 0; d < DHD; d += 4) {
                float4 kv = *(const float4*)(kr + d);
                sum = fmaf(qr[d],     kv.x, sum);
                sum = fmaf(qr[d + 1], kv.y, sum);
                sum = fmaf(qr[d + 2], kv.z, sum);
                sum = fmaf(qr[d + 3], kv.w, sum);
            }
            sc[kk] = sum;
        }
        float tmax = mrun;
#pragma unroll
        for (int kk = 0; kk < 32; kk++) tmax = fmaxf(tmax, sc[kk]);
        const float rescale = fexp(mrun - tmax);
        lrun *= rescale;
#pragma unroll
        for (int d = 0; d < DHD; d++) acc[d] *= rescale;
#pragma unroll
        for (int kk = 0; kk < 32; kk++) {
            const float w = fexp(sc[kk] - tmax);
            lrun += w;
            const float* vr = Vs + (kt + kk) * DHD;
#pragma unroll
            for (int d = 0; d < DHD; d += 4) {
                float4 vv = *(const float4*)(vr + d);
                acc[d]     = fmaf(w, vv.x, acc[d]);
                acc[d + 1] = fmaf(w, vv.y, acc[d + 1]);
                acc[d + 2] = fmaf(w, vv.z, acc[d + 2]);
                acc[d + 3] = fmaf(w, vv.w, acc[d + 3]);
            }
        }
        mrun = tmax;
    }

    const float inv = 1.0f / lrun;
    const int mrow = s * QL + tid;
    const float* gp = gbuf + mrow * CC + h * DHD;
    float* op = obuf + mrow * CC + h * DHD;
#pragma unroll
    for (int d = 0; d < DHD; d += 4) {
        float4 gg = *(const float4*)(gp + d);
        float4 ov;
        ov.x = acc[d]     * inv * gg.x;
        ov.y = acc[d + 1] * inv * gg.y;
        ov.z = acc[d + 2] * inv * gg.z;
        ov.w = acc[d + 3] * inv * gg.w;
        *(float4*)(op + d) = ov;
    }
}

// =================== launch ================================================
extern "C" void kernel_launch(void* const* d_in, const int* in_sizes, int n_in,
                              void* d_out, int out_size) {
    const float* q_x       = (const float*)d_in[0];
    const float* kv_x      = (const float*)d_in[1];
    const float* bias_mask = (const float*)d_in[2];
    const float* bias_pair = (const float*)d_in[3];
    const float* Wq        = (const float*)d_in[4];
    const float* Wk        = (const float*)d_in[5];
    const float* Wv        = (const float*)d_in[6];
    const float* Wg        = (const float*)d_in[7];
    const float* bg        = (const float*)d_in[8];
    const float* Wo        = (const float*)d_in[9];
    const float* bo        = (const float*)d_in[10];
    float* out = (float*)d_out;

    float *qb, *kb, *vb, *gb, *ob, *bpT;
    uint4 *qxA, *kvxA, *oA, *WqB, *WkB, *WvB, *WgB, *WoB;
    cudaGetSymbolAddress((void**)&qb,   g_q);
    cudaGetSymbolAddress((void**)&kb,   g_k);
    cudaGetSymbolAddress((void**)&vb,   g_v);
    cudaGetSymbolAddress((void**)&gb,   g_g);
    cudaGetSymbolAddress((void**)&ob,   g_o);
    cudaGetSymbolAddress((void**)&bpT,  g_bpT);
    cudaGetSymbolAddress((void**)&qxA,  g_qxA);
    cudaGetSymbolAddress((void**)&kvxA, g_kvxA);
    cudaGetSymbolAddress((void**)&oA,   g_oA);
    cudaGetSymbolAddress((void**)&WqB,  g_WqB);
    cudaGetSymbolAddress((void**)&WkB,  g_WkB);
    cudaGetSymbolAddress((void**)&WvB,  g_WvB);
    cudaGetSymbolAddress((void**)&WgB,  g_WgB);
    cudaGetSymbolAddress((void**)&WoB,  g_WoB);

    const int nA = M_TOT * KU2;              // 4194304 uint2 outputs
    packA_k<<<nA / 256, 256>>>(q_x,  (uint2*)qxA);
    packA_k<<<nA / 256, 256>>>(kv_x, (uint2*)kvxA);
    packB5_k<<<dim3(64, 5), 256>>>(Wq, Wk, Wv, Wg, Wo);
    transBP_k<<<dim3(8, 8, HH), 256>>>(bias_pair, bpT);

    const dim3 grid(CC / 128, M_TOT / 64);   // (2, 512)
    gemm_mma<0><<<grid, 128>>>(qxA,  WqB, nullptr, qb);
    gemm_mma<0><<<grid, 128>>>(kvxA, WkB, nullptr, kb);
    gemm_mma<0><<<grid, 128>>>(kvxA, WvB, nullptr, vb);
    gemm_mma<1><<<grid, 128>>>(qxA,  WgB, bg,      gb);

    const int smem_attn = (2 * QL * DHD + QL) * (int)sizeof(float);  // 66.5 KB
    cudaFuncSetAttribute(attn_k, cudaFuncAttributeMaxDynamicSharedMemorySize, smem_attn);
    attn_k<<<SS * HH, 256, smem_attn>>>(qb, kb, vb, bias_mask, bpT, gb, ob);

    packA_k<<<nA / 256, 256>>>(ob, (uint2*)oA);
    gemm_mma<2><<<grid, 128>>>(oA, WoB, bo, out);
}